// round 8
// baseline (speedup 1.0000x reference)
#include <cuda_runtime.h>

// FullyConnectedTensorProduct: B=2^20, MUL=8, DIM=32, 4 paths of 8x8x8.
// R8: weights in __constant__; E=2 elements/thread so each LDC.128 feeds two
// elements -> constant-port pressure halves (R6 was LDC-bound at 128 cyc/elem,
// FMA needs only ~92). Phased to bound registers: W1 -> W0 (store o0 early)
// -> W3 -> W2 (store o1). Inputs/outputs transpose-staged through stride-65
// padded smem. fma.rn.f32x2 packs adjacent w. ALPHA folded at staging,
// INV_SQRT3 into W1's v1 reads.

typedef unsigned long long u64;

#define ALPHA_F     0.08838834764831845f   /* 1/sqrt(128) */
#define INV_SQRT3_F 0.5773502691896258f
#define EPITCH 65

__constant__ __align__(16) float cw[2048];  // raw weights (8 KB)

static __device__ __forceinline__ u64 pk2(float lo, float hi) {
    u64 r;
    asm("mov.b64 %0, {%1, %2};"
        : "=l"(r) : "r"(__float_as_uint(lo)), "r"(__float_as_uint(hi)));
    return r;
}
static __device__ __forceinline__ u64 dup2(float x) { return pk2(x, x); }
static __device__ __forceinline__ void upk2(u64 v, float& lo, float& hi) {
    unsigned l_, h_;
    asm("mov.b64 {%0, %1}, %2;" : "=r"(l_), "=r"(h_) : "l"(v));
    lo = __uint_as_float(l_);
    hi = __uint_as_float(h_);
}
static __device__ __forceinline__ u64 ffma2(u64 a, u64 b, u64 c) {
    u64 d;
    asm("fma.rn.f32x2 %0, %1, %2, %3;" : "=l"(d) : "l"(a), "l"(b), "l"(c));
    return d;
}

// a0/a1 += s0/s1 * cw[off..off+7]: one LDC pair feeds both elements
static __device__ __forceinline__ void wacc2(int off, u64 s0, u64 s1,
                                             u64 a0[4], u64 a1[4]) {
    ulonglong2 q0 = *(const ulonglong2*)(cw + off);
    ulonglong2 q1 = *(const ulonglong2*)(cw + off + 4);
    a0[0] = ffma2(s0, q0.x, a0[0]);
    a1[0] = ffma2(s1, q0.x, a1[0]);
    a0[1] = ffma2(s0, q0.y, a0[1]);
    a1[1] = ffma2(s1, q0.y, a1[1]);
    a0[2] = ffma2(s0, q1.x, a0[2]);
    a1[2] = ffma2(s1, q1.x, a1[2]);
    a0[3] = ffma2(s0, q1.y, a0[3]);
    a1[3] = ffma2(s1, q1.y, a1[3]);
}

__global__ __launch_bounds__(128, 3)
void fctp_kernel(const float* __restrict__ x1,
                 const float* __restrict__ x2,
                 float* __restrict__ out)
{
    extern __shared__ __align__(16) float st[];   // 256 * EPITCH staging

    const int tid = threadIdx.x;
    const size_t eBase = (size_t)blockIdx.x * 256;

    // ---- stage inputs: x1*ALPHA at [e*65+0..31], x2 at [e*65+32..63] ----
    {
        const float4* g1 = (const float4*)(x1 + eBase * 32);
        const float4* g2 = (const float4*)(x2 + eBase * 32);
#pragma unroll
        for (int c = 0; c < 16; c++) {
            int lin = tid + c * 128;          // float4 index in [0,2048)
            int e = lin >> 3, j = (lin & 7) << 2;
            float4 a = g1[lin];
            float* p = st + e * EPITCH + j;
            p[0] = a.x * ALPHA_F; p[1] = a.y * ALPHA_F;
            p[2] = a.z * ALPHA_F; p[3] = a.w * ALPHA_F;
            float4 b = g2[lin];
            float* q = st + e * EPITCH + 32 + j;
            q[0] = b.x; q[1] = b.y; q[2] = b.z; q[3] = b.w;
        }
    }
    __syncthreads();

    float* S0 = st + tid * EPITCH;
    float* S1 = st + (tid + 128) * EPITCH;

    // ======== phase A: W1: out0[w] += INV3*(v1[u].v2[v]) * W1[u,v,w] ========
    u64 o0[2][4] = {};
    {
        float v2l[2][24];
#pragma unroll
        for (int i = 0; i < 24; i++) {
            v2l[0][i] = S0[40 + i];
            v2l[1][i] = S1[40 + i];
        }
#pragma unroll
        for (int u = 0; u < 8; u++) {
            float b00 = S0[8 + u * 3 + 0] * INV_SQRT3_F;
            float b01 = S0[8 + u * 3 + 1] * INV_SQRT3_F;
            float b02 = S0[8 + u * 3 + 2] * INV_SQRT3_F;
            float b10 = S1[8 + u * 3 + 0] * INV_SQRT3_F;
            float b11 = S1[8 + u * 3 + 1] * INV_SQRT3_F;
            float b12 = S1[8 + u * 3 + 2] * INV_SQRT3_F;
#pragma unroll
            for (int v = 0; v < 8; v++) {
                float p0 = b00 * v2l[0][v * 3 + 0];
                p0 = fmaf(b01, v2l[0][v * 3 + 1], p0);
                p0 = fmaf(b02, v2l[0][v * 3 + 2], p0);
                float p1 = b10 * v2l[1][v * 3 + 0];
                p1 = fmaf(b11, v2l[1][v * 3 + 1], p1);
                p1 = fmaf(b12, v2l[1][v * 3 + 2], p1);
                u64 pd0 = dup2(p0), pd1 = dup2(p1);
                const int off = 512 + u * 64 + v * 8;
                ulonglong2 q0 = *(const ulonglong2*)(cw + off);
                ulonglong2 q1 = *(const ulonglong2*)(cw + off + 4);
                o0[0][0] = ffma2(pd0, q0.x, o0[0][0]);
                o0[1][0] = ffma2(pd1, q0.x, o0[1][0]);
                o0[0][1] = ffma2(pd0, q0.y, o0[0][1]);
                o0[1][1] = ffma2(pd1, q0.y, o0[1][1]);
                o0[0][2] = ffma2(pd0, q1.x, o0[0][2]);
                o0[1][2] = ffma2(pd1, q1.x, o0[1][2]);
                o0[0][3] = ffma2(pd0, q1.y, o0[0][3]);
                o0[1][3] = ffma2(pd1, q1.y, o0[1][3]);
            }
        }
    }

    // ======== dup scalar inputs (live across o0 store) ========
    u64 s1d[2][8], s2d[2][8];
#pragma unroll
    for (int u = 0; u < 8; u++) {
        s1d[0][u] = dup2(S0[u]);
        s1d[1][u] = dup2(S1[u]);
    }
#pragma unroll
    for (int v = 0; v < 8; v++) {
        s2d[0][v] = dup2(S0[32 + v]);
        s2d[1][v] = dup2(S1[32 + v]);
    }

    // ======== phase B: W0: out0[w] += s2[v] * (sum_u s1[u] * W0[u,v,w]) ========
#pragma unroll
    for (int v = 0; v < 8; v++) {
        u64 a[2][4] = {};
#pragma unroll
        for (int u = 0; u < 8; u++)
            wacc2(u * 64 + v * 8, s1d[0][u], s1d[1][u], a[0], a[1]);
#pragma unroll
        for (int i = 0; i < 4; i++) {
            o0[0][i] = ffma2(s2d[0][v], a[0][i], o0[0][i]);
            o0[1][i] = ffma2(s2d[1][v], a[1][i], o0[1][i]);
        }
    }

    // ---- store o0 -> S[0..7] now (s1 lives in regs); frees 16 regs ----
#pragma unroll
    for (int je = 0; je < 2; je++) {
        float* S = je ? S1 : S0;
        float r0, r1;
        upk2(o0[je][0], r0, r1); S[0] = r0; S[1] = r1;
        upk2(o0[je][1], r0, r1); S[2] = r0; S[3] = r1;
        upk2(o0[je][2], r0, r1); S[4] = r0; S[5] = r1;
        upk2(o0[je][3], r0, r1); S[6] = r0; S[7] = r1;
    }

    // ======== phase C: W3: out1[w,k] += v1[u,k] * (sum_v s2[v] * W3[u,v,w]) ========
    u64 o1[2][3][4] = {};
#pragma unroll
    for (int u = 0; u < 8; u++) {
        u64 a[2][4] = {};
#pragma unroll
        for (int v = 0; v < 8; v++)
            wacc2(1536 + u * 64 + v * 8, s2d[0][v], s2d[1][v], a[0], a[1]);
#pragma unroll
        for (int k = 0; k < 3; k++) {
            u64 t0 = dup2(S0[8 + u * 3 + k]);   // v1 (has ALPHA)
            u64 t1 = dup2(S1[8 + u * 3 + k]);
#pragma unroll
            for (int wp = 0; wp < 4; wp++) {
                o1[0][k][wp] = ffma2(t0, a[0][wp], o1[0][k][wp]);
                o1[1][k][wp] = ffma2(t1, a[1][wp], o1[1][k][wp]);
            }
        }
    }

    // ======== phase D: W2: out1[w,k] += v2[v,k] * (sum_u s1[u] * W2[u,v,w]) ========
#pragma unroll
    for (int v = 0; v < 8; v++) {
        u64 a[2][4] = {};
#pragma unroll
        for (int u = 0; u < 8; u++)
            wacc2(1024 + u * 64 + v * 8, s1d[0][u], s1d[1][u], a[0], a[1]);
#pragma unroll
        for (int k = 0; k < 3; k++) {
            u64 t0 = dup2(S0[40 + v * 3 + k]);  // v2
            u64 t1 = dup2(S1[40 + v * 3 + k]);
#pragma unroll
            for (int wp = 0; wp < 4; wp++) {
                o1[0][k][wp] = ffma2(t0, a[0][wp], o1[0][k][wp]);
                o1[1][k][wp] = ffma2(t1, a[1][wp], o1[1][k][wp]);
            }
        }
    }

    // ---- store o1 -> S[8..31] (v1 dead, v2 done) ----
#pragma unroll
    for (int je = 0; je < 2; je++) {
        float* S = je ? S1 : S0;
#pragma unroll
        for (int k = 0; k < 3; k++)
#pragma unroll
            for (int wp = 0; wp < 4; wp++) {
                float lo, hi;
                upk2(o1[je][k][wp], lo, hi);
                S[8 + (2 * wp)     * 3 + k] = lo;
                S[8 + (2 * wp + 1) * 3 + k] = hi;
            }
    }

    __syncthreads();

    // ---- coalesced drain of S[0..31] per element ----
    {
        float4* go = (float4*)(out + eBase * 32);
#pragma unroll
        for (int c = 0; c < 16; c++) {
            int lin = tid + c * 128;
            int e = lin >> 3, j = (lin & 7) << 2;
            const float* p = st + e * EPITCH + j;
            go[lin] = make_float4(p[0], p[1], p[2], p[3]);
        }
    }
}

extern "C" void kernel_launch(void* const* d_in, const int* in_sizes, int n_in,
                              void* d_out, int out_size)
{
    const float* x1 = (const float*)d_in[0];
    const float* x2 = (const float*)d_in[1];
    const float* wt = (const float*)d_in[2];
    float* out = (float*)d_out;

    // Copy raw weights into constant memory (D2D async: graph-capturable).
    cudaMemcpyToSymbolAsync(cw, wt, 2048 * sizeof(float), 0,
                            cudaMemcpyDeviceToDevice, 0);

    int nelem  = out_size / 32;                     // 2^20
    int blocks = nelem / 256;                       // 256 elements per block
    size_t smem = (256 * EPITCH) * sizeof(float);   // 66560 B

    static bool attr_set = false;
    if (!attr_set) {
        cudaFuncSetAttribute(fctp_kernel,
                             cudaFuncAttributeMaxDynamicSharedMemorySize,
                             (int)smem);
        attr_set = true;
    }
    fctp_kernel<<<blocks, 128, smem>>>(x1, x2, out);
}

// round 9
// speedup vs baseline: 2.1389x; 2.1389x over previous
#include <cuda_runtime.h>

// FullyConnectedTensorProduct: B=2^20, MUL=8, DIM=32, 4 paths of 8x8x8.
// R9: R6 structure (E=1, 96 regs, 5 blocks/SM) with weight loads SPLIT across
// ports: W1 (INV_SQRT3 pre-folded) + W0[u<2] in shared (L1 crossbar), the
// remaining ~2/3 in __constant__ (const port, floor 8/LDC was R6's binder).
// Balances LDC ~152K, LDS ~138K, FMA ~156K cyc -> FMA-bound.
// Inputs/outputs transpose-staged through stride-65 padded smem.

typedef unsigned long long u64;

#define ALPHA_F     0.08838834764831845f   /* 1/sqrt(128) */
#define INV_SQRT3_F 0.5773502691896258f
#define EPITCH 65
#define WSH_N 640                          /* 128 (W0 u<2) + 512 (W1) */

__constant__ __align__(16) float cw[2048];  // raw weights (8 KB)

static __device__ __forceinline__ u64 pk2(float lo, float hi) {
    u64 r;
    asm("mov.b64 %0, {%1, %2};"
        : "=l"(r) : "r"(__float_as_uint(lo)), "r"(__float_as_uint(hi)));
    return r;
}
static __device__ __forceinline__ u64 dup2(float x) { return pk2(x, x); }
static __device__ __forceinline__ void upk2(u64 v, float& lo, float& hi) {
    unsigned l_, h_;
    asm("mov.b64 {%0, %1}, %2;" : "=r"(l_), "=r"(h_) : "l"(v));
    lo = __uint_as_float(l_);
    hi = __uint_as_float(h_);
}
static __device__ __forceinline__ u64 ffma2(u64 a, u64 b, u64 c) {
    u64 d;
    asm("fma.rn.f32x2 %0, %1, %2, %3;" : "=l"(d) : "l"(a), "l"(b), "l"(c));
    return d;
}

// a[0..3] += s * cw[off..off+7]  (const port)
static __device__ __forceinline__ void wacc1(int off, u64 s, u64 a[4]) {
    ulonglong2 q0 = *(const ulonglong2*)(cw + off);
    ulonglong2 q1 = *(const ulonglong2*)(cw + off + 4);
    a[0] = ffma2(s, q0.x, a[0]);
    a[1] = ffma2(s, q0.y, a[1]);
    a[2] = ffma2(s, q1.x, a[2]);
    a[3] = ffma2(s, q1.y, a[3]);
}
// a[0..3] += s * wp[0..7]  (shared / L1 crossbar)
static __device__ __forceinline__ void waccS(const float* wp, u64 s, u64 a[4]) {
    ulonglong2 q0 = *(const ulonglong2*)wp;
    ulonglong2 q1 = *(const ulonglong2*)(wp + 4);
    a[0] = ffma2(s, q0.x, a[0]);
    a[1] = ffma2(s, q0.y, a[1]);
    a[2] = ffma2(s, q1.x, a[2]);
    a[3] = ffma2(s, q1.y, a[3]);
}

__global__ __launch_bounds__(128, 5)
void fctp_kernel(const float* __restrict__ x1,
                 const float* __restrict__ x2,
                 const float* __restrict__ wt,
                 float* __restrict__ out)
{
    extern __shared__ __align__(16) float smem[];
    float* wsh = smem;             // 640 floats: W0[u<2] raw, then W1*INV_SQRT3
    float* st  = smem + WSH_N;     // 128 * EPITCH staging

    const int tid = threadIdx.x;
    const size_t eBase = (size_t)blockIdx.x * 128;

    // ---- stage smem weights: [0:128)=wt[0:128), [128:640)=wt[512:1024)*INV3 ----
#pragma unroll
    for (int c = 0; c < 5; c++) {
        int i = tid + c * 128;
        wsh[i] = (i < 128) ? __ldg(wt + i)
                           : __ldg(wt + 384 + i) * INV_SQRT3_F;
    }

    // ---- stage inputs: x1*ALPHA at [e*65+0..31], x2 at [e*65+32..63] ----
    {
        const float4* g1 = (const float4*)(x1 + eBase * 32);
        const float4* g2 = (const float4*)(x2 + eBase * 32);
#pragma unroll
        for (int c = 0; c < 8; c++) {
            int lin = tid + c * 128;
            int e = lin >> 3, j = (lin & 7) << 2;
            float4 a = g1[lin];
            float* p = st + e * EPITCH + j;
            p[0] = a.x * ALPHA_F; p[1] = a.y * ALPHA_F;
            p[2] = a.z * ALPHA_F; p[3] = a.w * ALPHA_F;
            float4 b = g2[lin];
            float* q = st + e * EPITCH + 32 + j;
            q[0] = b.x; q[1] = b.y; q[2] = b.z; q[3] = b.w;
        }
    }
    __syncthreads();

    const float* S = st + tid * EPITCH;

    u64 o0[4] = {};
    u64 o1[3][4] = {};

    // ======== phase A: W0 + W2 (contract u against s1) ========
    {
        u64 s1d[8];
#pragma unroll
        for (int u = 0; u < 8; u++) s1d[u] = dup2(S[u]);

        // W0: u=0,1 from shared; u=2..7 from const
#pragma unroll
        for (int v = 0; v < 8; v++) {
            u64 a[4] = {};
            waccS(&wsh[0 * 64 + v * 8], s1d[0], a);
            waccS(&wsh[1 * 64 + v * 8], s1d[1], a);
#pragma unroll
            for (int u = 2; u < 8; u++)
                wacc1(u * 64 + v * 8, s1d[u], a);
            u64 t = dup2(S[32 + v]);
#pragma unroll
            for (int i = 0; i < 4; i++) o0[i] = ffma2(t, a[i], o0[i]);
        }

        // W2 (const): out1[w,k] += v2[v,k] * (sum_u s1[u] * W2[u,v,w])
#pragma unroll
        for (int v = 0; v < 8; v++) {
            u64 a[4] = {};
#pragma unroll
            for (int u = 0; u < 8; u++)
                wacc1(1024 + u * 64 + v * 8, s1d[u], a);
#pragma unroll
            for (int k = 0; k < 3; k++) {
                u64 t = dup2(S[40 + v * 3 + k]);
#pragma unroll
                for (int wp = 0; wp < 4; wp++)
                    o1[k][wp] = ffma2(t, a[wp], o1[k][wp]);
            }
        }
    }

    // ======== phase B: W3 (const; contract v against s2) ========
    {
        u64 s2d[8];
#pragma unroll
        for (int v = 0; v < 8; v++) s2d[v] = dup2(S[32 + v]);
#pragma unroll
        for (int u = 0; u < 8; u++) {
            u64 a[4] = {};
#pragma unroll
            for (int v = 0; v < 8; v++)
                wacc1(1536 + u * 64 + v * 8, s2d[v], a);
#pragma unroll
            for (int k = 0; k < 3; k++) {
                u64 t = dup2(S[8 + u * 3 + k]);
#pragma unroll
                for (int wp = 0; wp < 4; wp++)
                    o1[k][wp] = ffma2(t, a[wp], o1[k][wp]);
            }
        }
    }

    // ======== phase C: W1 (shared, INV_SQRT3 folded) ========
    {
        float v2l[24];
#pragma unroll
        for (int i = 0; i < 24; i++) v2l[i] = S[40 + i];
#pragma unroll
        for (int u = 0; u < 8; u++) {
            float a0 = S[8 + u * 3 + 0];
            float a1 = S[8 + u * 3 + 1];
            float a2 = S[8 + u * 3 + 2];
#pragma unroll
            for (int v = 0; v < 8; v++) {
                float p = a0 * v2l[v * 3 + 0];
                p = fmaf(a1, v2l[v * 3 + 1], p);
                p = fmaf(a2, v2l[v * 3 + 2], p);
                u64 pd = dup2(p);
                const float* wp = &wsh[128 + u * 64 + v * 8];
                ulonglong2 q0 = *(const ulonglong2*)wp;
                ulonglong2 q1 = *(const ulonglong2*)(wp + 4);
                o0[0] = ffma2(pd, q0.x, o0[0]);
                o0[1] = ffma2(pd, q0.y, o0[1]);
                o0[2] = ffma2(pd, q1.x, o0[2]);
                o0[3] = ffma2(pd, q1.y, o0[3]);
            }
        }
    }

    // ======== write outputs into own staging row, then coalesced drain ========
    __syncthreads();   // everyone done reading st before overwrite
    {
        float r[32];
        upk2(o0[0], r[0], r[1]); upk2(o0[1], r[2], r[3]);
        upk2(o0[2], r[4], r[5]); upk2(o0[3], r[6], r[7]);
#pragma unroll
        for (int k = 0; k < 3; k++)
#pragma unroll
            for (int wp = 0; wp < 4; wp++) {
                float lo, hi;
                upk2(o1[k][wp], lo, hi);
                r[8 + (2 * wp)     * 3 + k] = lo;
                r[8 + (2 * wp + 1) * 3 + k] = hi;
            }
        float* P = st + tid * EPITCH;
#pragma unroll
        for (int f = 0; f < 32; f++) P[f] = r[f];
    }
    __syncthreads();
    {
        float4* go = (float4*)(out + eBase * 32);
#pragma unroll
        for (int c = 0; c < 8; c++) {
            int lin = tid + c * 128;
            int e = lin >> 3, j = (lin & 7) << 2;
            const float* p = st + e * EPITCH + j;
            go[lin] = make_float4(p[0], p[1], p[2], p[3]);
        }
    }
}

extern "C" void kernel_launch(void* const* d_in, const int* in_sizes, int n_in,
                              void* d_out, int out_size)
{
    const float* x1 = (const float*)d_in[0];
    const float* x2 = (const float*)d_in[1];
    const float* wt = (const float*)d_in[2];
    float* out = (float*)d_out;

    // Copy raw weights into constant memory (D2D async: graph-capturable).
    cudaMemcpyToSymbolAsync(cw, wt, 2048 * sizeof(float), 0,
                            cudaMemcpyDeviceToDevice, 0);

    int nelem  = out_size / 32;                            // 2^20
    int blocks = nelem / 128;                              // 128 elements/block
    size_t smem = (WSH_N + 128 * EPITCH) * sizeof(float);  // 35840 B

    static bool attr_set = false;
    if (!attr_set) {
        cudaFuncSetAttribute(fctp_kernel,
                             cudaFuncAttributeMaxDynamicSharedMemorySize,
                             (int)smem);
        attr_set = true;
    }
    fctp_kernel<<<blocks, 128, smem>>>(x1, x2, wt, out);
}